// round 1
// baseline (speedup 1.0000x reference)
#include <cuda_runtime.h>
#include <cstdint>

#define V_BINS 1000001
#define N_ELEMS (65536 * 200)

// Device-side scratch flag (allocation-free): nonzero => ids are int32,
// zero => ids are int64 (all sampled high words were zero).
__device__ int g_any_odd_nonzero;

__global__ void reset_flag_kernel() {
    g_any_odd_nonzero = 0;
}

// Probe the id buffer read as 32-bit words. For little-endian int64 ids in
// [0, 1e6], every odd word (high half) is 0. For int32 random ids in
// [0, 1e6), the probability that 4096 sampled words are all zero is ~0.
// Only reads the first n_elems 32-bit words, which is in-bounds for both
// int32 (exactly the buffer) and int64 (first half of the buffer).
__global__ void detect_dtype_kernel(const int* __restrict__ words, long long n_elems) {
    const int tid = threadIdx.x;           // 256 threads, 16 samples each
    const long long n_samples = 4096;
    const long long stride = (n_elems / 2) / n_samples;  // spacing between sampled pairs
    int local_any = 0;
    #pragma unroll
    for (int s = 0; s < 16; s++) {
        long long k = (long long)tid * 16 + s;
        long long pos = 2 * (k * (stride > 0 ? stride : 1)) + 1;  // odd word index
        if (pos < n_elems) {
            if (words[pos] != 0) local_any = 1;
        }
    }
    if (local_any) atomicOr(&g_any_odd_nonzero, 1);
}

// out[0..V) = (float)i  (the arange(V) "idx" output)
// out[V..out_size) = 0  (the histogram accumulator, zero-initialized)
__global__ void init_out_kernel(float* __restrict__ out, int out_size) {
    int i = blockIdx.x * blockDim.x + threadIdx.x;
    if (i < out_size) {
        out[i] = (i < V_BINS) ? (float)i : 0.0f;
    }
}

// Histogram: 4 elements per thread, vectorized loads, L2 atomics (REDG).
__global__ void hist_kernel(const void* __restrict__ seq,
                            const float* __restrict__ ones,
                            float* __restrict__ cnt, int n) {
    const bool is64 = (g_any_odd_nonzero == 0);
    int i0 = (blockIdx.x * blockDim.x + threadIdx.x) * 4;
    if (i0 >= n) return;

    float4 o = *reinterpret_cast<const float4*>(ones + i0);

    if (is64) {
        const longlong2* p = reinterpret_cast<const longlong2*>(seq);
        longlong2 a = p[i0 / 2];
        longlong2 b = p[i0 / 2 + 1];
        atomicAdd(cnt + (int)a.x, o.x);
        atomicAdd(cnt + (int)a.y, o.y);
        atomicAdd(cnt + (int)b.x, o.z);
        atomicAdd(cnt + (int)b.y, o.w);
    } else {
        int4 a = reinterpret_cast<const int4*>(seq)[i0 / 4];
        atomicAdd(cnt + a.x, o.x);
        atomicAdd(cnt + a.y, o.y);
        atomicAdd(cnt + a.z, o.z);
        atomicAdd(cnt + a.w, o.w);
    }
}

extern "C" void kernel_launch(void* const* d_in, const int* in_sizes, int n_in,
                              void* d_out, int out_size) {
    const void*  seq  = d_in[0];
    const float* ones = (const float*)d_in[1];
    float* out = (float*)d_out;

    const int n = in_sizes[0];  // element count of item_seq (13,107,200)

    // 1) reset dtype-probe flag
    reset_flag_kernel<<<1, 1>>>();
    // 2) probe int32 vs int64 id encoding
    detect_dtype_kernel<<<1, 256>>>((const int*)seq, (long long)n);
    // 3) init output: idx = arange(V), cnt = 0
    {
        int threads = 256;
        int blocks = (out_size + threads - 1) / threads;
        init_out_kernel<<<blocks, threads>>>(out, out_size);
    }
    // 4) histogram into out[V..)
    {
        int threads = 256;
        int elems_per_block = threads * 4;
        int blocks = (n + elems_per_block - 1) / elems_per_block;
        hist_kernel<<<blocks, threads>>>(seq, ones, out + V_BINS, n);
    }
}

// round 2
// speedup vs baseline: 1.0497x; 1.0497x over previous
#include <cuda_runtime.h>
#include <cstdint>

#define V_BINS 1000001

// Dtype-probe flag: 1 => ids are int32, 0 => ids are int64.
// Deterministic: reset + probe happen in an ordered single block each call.
__device__ int g_ids_are_int32;

// Fused kernel: block 0 additionally performs the dtype probe (reset -> sample
// -> reduce), all blocks vectorized-init the output:
//   out[0..V)        = (float)i   (idx = arange(V))
//   out[V..out_size) = 0          (histogram accumulator)
__global__ void init_and_probe_kernel(float* __restrict__ out, int out_size,
                                      const int* __restrict__ words,
                                      long long n_elems) {
    // ---- probe (block 0 only; fully ordered within the block) ----
    if (blockIdx.x == 0) {
        if (threadIdx.x == 0) g_ids_are_int32 = 0;
        __syncthreads();
        // Sample odd 32-bit words: for little-endian int64 ids in [0,1e6]
        // every odd word is 0; for int32 random ids essentially never all 0.
        const long long n_samples = 4096;
        long long stride = (n_elems / 2) / n_samples;
        if (stride < 1) stride = 1;
        int local_any = 0;
        #pragma unroll
        for (int s = 0; s < 16; s++) {
            long long k = (long long)threadIdx.x * 16 + s;
            long long pos = 2 * (k * stride) + 1;
            if (pos < n_elems && words[pos] != 0) local_any = 1;
        }
        unsigned any = __ballot_sync(0xFFFFFFFFu, local_any);
        if ((threadIdx.x & 31) == 0 && any) atomicOr(&g_ids_are_int32, 1);
        __syncthreads();
    }

    // ---- vectorized init (all blocks) ----
    int i4 = (blockIdx.x * blockDim.x + threadIdx.x) * 4;
    if (i4 + 3 < out_size) {
        float4 v;
        v.x = (i4 + 0 < V_BINS) ? (float)(i4 + 0) : 0.0f;
        v.y = (i4 + 1 < V_BINS) ? (float)(i4 + 1) : 0.0f;
        v.z = (i4 + 2 < V_BINS) ? (float)(i4 + 2) : 0.0f;
        v.w = (i4 + 3 < V_BINS) ? (float)(i4 + 3) : 0.0f;
        *reinterpret_cast<float4*>(out + i4) = v;
    } else {
        for (int i = i4; i < out_size; i++)
            out[i] = (i < V_BINS) ? (float)i : 0.0f;
    }
}

// Histogram: 8 elements per thread, streaming (evict-first) loads so the 4MB
// histogram stays L2-resident; spread-address REDG.ADD.F32 atomics.
__global__ void hist_kernel(const void* __restrict__ seq,
                            const float* __restrict__ ones,
                            float* __restrict__ cnt, int n) {
    const bool is32 = (g_ids_are_int32 != 0);
    int i0 = (blockIdx.x * blockDim.x + threadIdx.x) * 8;
    if (i0 >= n) return;

    if (i0 + 8 <= n) {
        float4 o0 = __ldcs(reinterpret_cast<const float4*>(ones + i0));
        float4 o1 = __ldcs(reinterpret_cast<const float4*>(ones + i0 + 4));
        if (is32) {
            int4 a = __ldcs(reinterpret_cast<const int4*>(seq) + i0 / 4);
            int4 b = __ldcs(reinterpret_cast<const int4*>(seq) + i0 / 4 + 1);
            atomicAdd(cnt + a.x, o0.x);
            atomicAdd(cnt + a.y, o0.y);
            atomicAdd(cnt + a.z, o0.z);
            atomicAdd(cnt + a.w, o0.w);
            atomicAdd(cnt + b.x, o1.x);
            atomicAdd(cnt + b.y, o1.y);
            atomicAdd(cnt + b.z, o1.z);
            atomicAdd(cnt + b.w, o1.w);
        } else {
            const longlong2* p = reinterpret_cast<const longlong2*>(seq);
            longlong2 q0 = __ldcs(p + i0 / 2);
            longlong2 q1 = __ldcs(p + i0 / 2 + 1);
            longlong2 q2 = __ldcs(p + i0 / 2 + 2);
            longlong2 q3 = __ldcs(p + i0 / 2 + 3);
            atomicAdd(cnt + (int)q0.x, o0.x);
            atomicAdd(cnt + (int)q0.y, o0.y);
            atomicAdd(cnt + (int)q1.x, o0.z);
            atomicAdd(cnt + (int)q1.y, o0.w);
            atomicAdd(cnt + (int)q2.x, o1.x);
            atomicAdd(cnt + (int)q2.y, o1.y);
            atomicAdd(cnt + (int)q3.x, o1.z);
            atomicAdd(cnt + (int)q3.y, o1.w);
        }
    } else {
        // tail (n not divisible by 8)
        for (int i = i0; i < n; i++) {
            float o = ones[i];
            int id = is32 ? reinterpret_cast<const int*>(seq)[i]
                          : (int)reinterpret_cast<const long long*>(seq)[i];
            atomicAdd(cnt + id, o);
        }
    }
}

extern "C" void kernel_launch(void* const* d_in, const int* in_sizes, int n_in,
                              void* d_out, int out_size) {
    const void*  seq  = d_in[0];
    const float* ones = (const float*)d_in[1];
    float* out = (float*)d_out;

    const int n = in_sizes[0];  // 13,107,200

    // 1) fused init (idx + zero cnt) + dtype probe
    {
        int threads = 256;
        int elems_per_block = threads * 4;
        int blocks = (out_size + elems_per_block - 1) / elems_per_block;
        init_and_probe_kernel<<<blocks, threads>>>(out, out_size,
                                                   (const int*)seq, (long long)n);
    }
    // 2) histogram into out[V..)
    {
        int threads = 256;
        int elems_per_block = threads * 8;
        int blocks = (n + elems_per_block - 1) / elems_per_block;
        hist_kernel<<<blocks, threads>>>(seq, ones, out + V_BINS, n);
    }
}